// round 10
// baseline (speedup 1.0000x reference)
#include <cuda_runtime.h>
#include <math.h>

#define NT 1024

// Fused TT-network:  y = log_softmax( x_pad @ W1_tt @ W2_tt )
// TT x TT (matching modes) = TT with cores G_k = contract_n(c1_k, c2_k).
// Zero-pad 177->3072 => only m1=m2=0 contribute; x zero-tail => m3>=6 dead.
//
// R10: 2 INDEPENDENT blocks (no cluster), 32 batch rows each; W is never
// materialized: logits = sum_{m3,r3} A3[m3,c,r3] * V[b,m3,r3] with
// V[b,m3,r3] = sum_idx x[b,32*m3+idx] * G34[r3,idx], V computed in parallel
// with A3. Critical path: P0 -> P1 -> P2 -> P3 (4 phases, 3 syncthreads).
__global__ __launch_bounds__(NT) void tt_fused_kernel(
    const float* __restrict__ x,     // (64,177)
    const float* __restrict__ c1_0,  // (1,3,10,3)
    const float* __restrict__ c1_1,  // (3,4,20,3)
    const float* __restrict__ c1_2,  // (3,8,50,3)
    const float* __restrict__ c1_3,  // (3,4,20,3)
    const float* __restrict__ c1_4,  // (3,8,10,1)
    const float* __restrict__ c2_0,  // (1,10,1,3)
    const float* __restrict__ c2_1,  // (3,20,2,3)
    const float* __restrict__ c2_2,  // (3,50,5,3)
    const float* __restrict__ c2_3,  // (3,20,1,3)
    const float* __restrict__ c2_4,  // (3,10,1,1)
    float* __restrict__ out)         // (64,10)
{
    __shared__ float sG1[162];    // [r1(9), p2(2), r2(9)]  (m2=0 slice)
    __shared__ float sG2[3240];   // [u(72)][v(45)]
    __shared__ float sG3[324];    // [r3, m4, r4]
    __shared__ float sG4[72];     // [r4, m5]
    __shared__ float sG34i[288];  // [idx(32)=m4*8+m5][r3(9)]
    __shared__ float sA1[9];
    __shared__ float sA2[18];     // [p2, r2]
    __shared__ float sBUF[5850];  // P0-P1: sC1(3600)+sC2(2250); P2+: sA3(540)+sV(1728)

    float* sC1 = sBUF;            // staged c1_2
    float* sC2 = sBUF + 3600;     // staged c2_2
    float* sA3 = sBUF;            // [m3(6)*90 + c*9 + r3]   (after P1)
    float* sV  = sBUF + 540;      // [b(32)*54 + m3*9 + r3]  (after P1)

    const int tid = threadIdx.x;

    // ---------- x prefetch: 32 rows per block, 16 lanes per row ------------
    const int bl = tid >> 4, s5 = tid & 15;          // bl: local batch row
    const int bg = bl + 32 * (int)blockIdx.x;        // global batch row
    float xv[12];
    if (tid < 512) {
        const float* xr = x + bg * 177;
        #pragma unroll
        for (int k = 0; k < 12; k++) {
            int j = s5 + 16 * k;
            xv[k] = (j < 177) ? __ldg(xr + j) : 0.f;
        }
    }

    // ---------- Phase 0: staging (t<512) | G3 | G4 | G1 | A1 ---------------
    if (tid < 512) {
        for (int i = tid; i < 3600; i += 512) sC1[i] = c1_2[i];
        for (int i = tid; i < 2250; i += 512) sC2[i] = c2_2[i];
        if (tid < 9) {
            // A1[r1] = sum_n c1_0[0,0,n,a1] * c2_0[0,n,0,b1]  (m1=0 only)
            int a1 = tid / 3, b1 = tid % 3;
            float acc = 0.f;
            #pragma unroll
            for (int n = 0; n < 10; n++) acc += c1_0[n * 3 + a1] * c2_0[n * 3 + b1];
            sA1[tid] = acc;
        }
    } else if (tid < 836) {
        // G3[r3,m4,r4]  (324)
        int o = tid - 512;
        int r4 = o % 9; int rest = o / 9;
        int m4 = rest % 4; int r3 = rest / 4;
        int a3 = r3 / 3, b3 = r3 % 3, a4 = r4 / 3, b4 = r4 % 3;
        const float* pa = c1_3 + (a3 * 4 + m4) * 60 + a4;  // n-stride 3
        const float* pb = c2_3 + b3 * 60 + b4;             // n-stride 3
        float acc = 0.f;
        #pragma unroll
        for (int n = 0; n < 20; n++) acc += pa[n * 3] * pb[n * 3];
        sG3[o] = acc;
    } else if (tid < 908) {
        // G4[r4,m5]  (72)
        int o = tid - 836;
        int m5 = o % 8, r4 = o / 8;
        int a4 = r4 / 3, b4 = r4 % 3;
        const float* pa = c1_4 + (a4 * 8 + m5) * 10;
        const float* pb = c2_4 + b4 * 10;
        float acc = 0.f;
        #pragma unroll
        for (int n = 0; n < 10; n++) acc += pa[n] * pb[n];
        sG4[r4 * 8 + m5] = acc;
    } else {
        // G1_0[r1,p2,r2]  (162 items over 116 threads)
        for (int o = tid - 908; o < 162; o += 116) {
            int r2 = o % 9, p2 = (o / 9) % 2, r1 = o / 18;
            int a1 = r1 / 3, b1 = r1 % 3, a2 = r2 / 3, b2 = r2 % 3;
            const float* pa = c1_1 + a1 * 240 + a2;          // m2=0, n-stride 3
            const float* pb = c2_1 + b1 * 120 + p2 * 3 + b2; // n-stride 6
            float acc = 0.f;
            #pragma unroll
            for (int n = 0; n < 20; n++) acc += pa[n * 3] * pb[n * 6];
            sG1[(r1 * 2 + p2) * 9 + r2] = acc;
        }
    }
    __syncthreads();

    // ---------- Phase 1: G2 (2x3 tiles) | G34i | A2 ------------------------
    if (tid < 540) {                       // 36 u-pairs x 15 v-triples
        int u0 = (tid / 15) * 2, v0 = (tid % 15) * 3;
        int abase0 = (u0 / 3) * 150 + (u0 % 3);
        int abase1 = ((u0 + 1) / 3) * 150 + ((u0 + 1) % 3);
        int bb = (v0 / 15) * 750 + (v0 % 15);   // consecutive v => +1,+2
        float a00 = 0.f, a01 = 0.f, a02 = 0.f, a10 = 0.f, a11 = 0.f, a12 = 0.f;
        #pragma unroll 5
        for (int k = 0; k < 50; k++) {
            float a0 = sC1[abase0 + k * 3];
            float a1 = sC1[abase1 + k * 3];
            float b0 = sC2[bb + k * 15];
            float b1 = sC2[bb + k * 15 + 1];
            float b2 = sC2[bb + k * 15 + 2];
            a00 = fmaf(a0, b0, a00); a01 = fmaf(a0, b1, a01); a02 = fmaf(a0, b2, a02);
            a10 = fmaf(a1, b0, a10); a11 = fmaf(a1, b1, a11); a12 = fmaf(a1, b2, a12);
        }
        sG2[u0 * 45 + v0] = a00; sG2[u0 * 45 + v0 + 1] = a01; sG2[u0 * 45 + v0 + 2] = a02;
        sG2[(u0 + 1) * 45 + v0] = a10; sG2[(u0 + 1) * 45 + v0 + 1] = a11; sG2[(u0 + 1) * 45 + v0 + 2] = a12;
    } else if (tid < 828) {
        // G34i[idx][r3] = sum_r4 G3[r3,m4,r4] * G4[r4,m5], idx = m4*8+m5 (288)
        int o = tid - 540;
        int r3 = o / 32, idx = o % 32;
        int m4 = idx / 8, m5 = idx % 8;
        float acc = 0.f;
        #pragma unroll
        for (int r4 = 0; r4 < 9; r4++)
            acc += sG3[(r3 * 4 + m4) * 9 + r4] * sG4[r4 * 8 + m5];
        sG34i[idx * 9 + r3] = acc;
    } else if (tid < 846) {
        // A2[p2,r2] = sum_r1 A1[r1] * G1_0[r1,p2,r2]  (18)
        int o = tid - 828;
        int r2 = o % 9, p2 = o / 9;
        float acc = 0.f;
        #pragma unroll
        for (int r1 = 0; r1 < 9; r1++)
            acc += sA1[r1] * sG1[(r1 * 2 + p2) * 9 + r2];
        sA2[p2 * 9 + r2] = acc;
    }
    __syncthreads();

    // ---------- Phase 2: V (t<512, shfl tree) | A3 (t>=512) ----------------
    if (tid < 512) {
        // V[bl,m3,r3] = sum_idx x[bl, 32*m3+idx] * G34i[idx][r3], m3<6.
        // j = 32*m3 + idx = s5 + 16*k with k=2*m3 (idx=s5) and k=2*m3+1 (idx=16+s5).
        float ga[9], gb[9];
        #pragma unroll
        for (int r3 = 0; r3 < 9; r3++) {
            ga[r3] = sG34i[s5 * 9 + r3];
            gb[r3] = sG34i[(16 + s5) * 9 + r3];
        }
        #pragma unroll
        for (int m3 = 0; m3 < 6; m3++) {
            float xa = xv[2 * m3], xb = xv[2 * m3 + 1];
            float part[9];
            #pragma unroll
            for (int r3 = 0; r3 < 9; r3++)
                part[r3] = fmaf(xa, ga[r3], xb * gb[r3]);
            #pragma unroll
            for (int off = 8; off > 0; off >>= 1)
                #pragma unroll
                for (int r3 = 0; r3 < 9; r3++)
                    part[r3] += __shfl_down_sync(0xffffffffu, part[r3], off, 16);
            if (s5 == 0) {
                #pragma unroll
                for (int r3 = 0; r3 < 9; r3++)
                    sV[bl * 54 + m3 * 9 + r3] = part[r3];
            }
        }
    } else {
        // A3[m3<6, c, r3] = sum_{a2,b2} A2[p2,(a2,b2)] * G2  (540 items)
        for (int o = tid - 512; o < 540; o += 512) {
            int m3 = o / 90; int rest = o % 90;
            int c = rest / 9; int r3 = rest % 9;
            int p2 = c / 5, p3 = c % 5;
            int a3 = r3 / 3, b3 = r3 % 3;
            float acc = 0.f;
            #pragma unroll
            for (int a2 = 0; a2 < 3; a2++)
                #pragma unroll
                for (int b2 = 0; b2 < 3; b2++)
                    acc += sA2[p2 * 9 + a2 * 3 + b2]
                         * sG2[(a2 * 24 + m3 * 3 + a3) * 45 + (b2 * 15 + p3 * 3 + b3)];
            sA3[o] = acc;   // o = m3*90 + c*9 + r3
        }
    }
    __syncthreads();

    // ---------- Phase 3: logits[bg,c] = sum_{m3,r3} A3 * V + log_softmax ---
    if (tid < 512) {
        // 54 (m3,r3) pairs split over 16 lanes: p = s5 + 16q.
        float acc[10];
        #pragma unroll
        for (int c = 0; c < 10; c++) acc[c] = 0.f;
        #pragma unroll
        for (int q = 0; q < 4; q++) {
            int p = s5 + 16 * q;
            if (p < 54) {
                int m3 = p / 9, r3 = p % 9;
                float v = sV[bl * 54 + p];
                const float* ar = sA3 + m3 * 90 + r3;   // + c*9
                #pragma unroll
                for (int c = 0; c < 10; c++)
                    acc[c] = fmaf(v, ar[c * 9], acc[c]);
            }
        }
        #pragma unroll
        for (int off = 8; off > 0; off >>= 1)
            #pragma unroll
            for (int c = 0; c < 10; c++)
                acc[c] += __shfl_down_sync(0xffffffffu, acc[c], off, 16);
        if (s5 == 0) {
            float m = -INFINITY;
            #pragma unroll
            for (int c = 0; c < 10; c++) m = fmaxf(m, acc[c]);
            float sum = 0.f;
            #pragma unroll
            for (int c = 0; c < 10; c++) sum += __expf(acc[c] - m);
            float lse = m + __logf(sum);
            #pragma unroll
            for (int c = 0; c < 10; c++) out[bg * 10 + c] = acc[c] - lse;
        }
    }
}

extern "C" void kernel_launch(void* const* d_in, const int* in_sizes, int n_in,
                              void* d_out, int out_size) {
    const float* x    = (const float*)d_in[0];
    const float* c1_0 = (const float*)d_in[1];
    const float* c1_1 = (const float*)d_in[2];
    const float* c1_2 = (const float*)d_in[3];
    const float* c1_3 = (const float*)d_in[4];
    const float* c1_4 = (const float*)d_in[5];
    const float* c2_0 = (const float*)d_in[6];
    const float* c2_1 = (const float*)d_in[7];
    const float* c2_2 = (const float*)d_in[8];
    const float* c2_3 = (const float*)d_in[9];
    const float* c2_4 = (const float*)d_in[10];
    float* out = (float*)d_out;

    tt_fused_kernel<<<2, NT>>>(x, c1_0, c1_1, c1_2, c1_3, c1_4,
                               c2_0, c2_1, c2_2, c2_3, c2_4, out);
}